// round 4
// baseline (speedup 1.0000x reference)
#include <cuda_runtime.h>
#include <cuda_fp16.h>
#include <cstdint>

// ---------------------------------------------------------------------------
// RoutedBitLinear: out[M,N] = x[M,K] @ (signs * blended_scales)[N,K]^T
// M=8192, N=4096, K=4096, group_size=128, P=8.
// mma.sync.m16n8k16 f16 path (tcgen05 unavailable: harness PTX target sm_103).
// R4: CTA tile 128x256, warp tile 64x64 (8 warps, 2x4). Cuts smem read
// traffic/FLOP 1.5x vs R3 (tensor was 70% busy, L1 59% -> smem phase stole
// tensor issue slots). 1 CTA/SM (128 acc regs/thread).
// ---------------------------------------------------------------------------

#define DM 8192
#define DN 4096
#define DK 4096
#define NGROUPS (DN * DK / 128)   // 131072

#define BM 128
#define BN 256
#define BK 32                      // halves per k-chunk
#define STAGES 4
#define NITER (DK / BK)            // 128
#define TILE_A_BYTES (BM * BK * 2) // 8192
#define TILE_B_BYTES (BN * BK * 2) // 16384
#define STAGE_BYTES (TILE_A_BYTES + TILE_B_BYTES)  // 24576
#define SMEM_TOTAL (STAGES * STAGE_BYTES)          // 98304

// Scratch (static device globals: allocation-free per harness rules)
__device__ __align__(256) __half g_Wh[(size_t)DN * DK];   // 32 MB
__device__ __align__(256) __half g_Xh[(size_t)DM * DK];   // 64 MB
__device__ float g_blend[NGROUPS];

// ------------------------------ helpers ------------------------------------
__device__ __forceinline__ uint32_t smem_u32(const void* p) {
    return (uint32_t)__cvta_generic_to_shared(p);
}
__device__ __forceinline__ void cp_async16(uint32_t dst, const void* src) {
    asm volatile("cp.async.cg.shared.global [%0], [%1], 16;" :: "r"(dst), "l"(src));
}
__device__ __forceinline__ void cp_commit() {
    asm volatile("cp.async.commit_group;");
}
template <int Npend>
__device__ __forceinline__ void cp_wait() {
    asm volatile("cp.async.wait_group %0;" :: "n"(Npend));
}
__device__ __forceinline__ void ldmx4(uint32_t* d, uint32_t addr) {
    asm volatile("ldmatrix.sync.aligned.m8n8.x4.shared.b16 {%0,%1,%2,%3}, [%4];"
                 : "=r"(d[0]), "=r"(d[1]), "=r"(d[2]), "=r"(d[3]) : "r"(addr));
}
__device__ __forceinline__ void mma16816(float* c, const uint32_t* a, const uint32_t* b) {
    asm volatile(
        "mma.sync.aligned.m16n8k16.row.col.f32.f16.f16.f32 "
        "{%0,%1,%2,%3}, {%4,%5,%6,%7}, {%8,%9}, {%0,%1,%2,%3};"
        : "+f"(c[0]), "+f"(c[1]), "+f"(c[2]), "+f"(c[3])
        : "r"(a[0]), "r"(a[1]), "r"(a[2]), "r"(a[3]), "r"(b[0]), "r"(b[1]));
}

// ------------------------------ prep kernels -------------------------------
__global__ void blend_kernel(const float* __restrict__ ps, const float* __restrict__ rt) {
    int g = blockIdx.x * 256 + threadIdx.x;
    float acc = 0.f;
#pragma unroll
    for (int p = 0; p < 8; p++)
        acc = fmaf(rt[p], ps[(size_t)p * NGROUPS + g], acc);
    g_blend[g] = acc;
}

__global__ void weight_kernel(const float* __restrict__ signs) {
    size_t base = ((size_t)blockIdx.x * 256 + threadIdx.x) * 8;
    float s = g_blend[base >> 7];  // flat index >> 7 == o*32 + i/128
    float4 a = *(const float4*)(signs + base);
    float4 b = *(const float4*)(signs + base + 4);
    union { __half2 h[4]; uint4 u; } pk;
    pk.h[0] = __floats2half2_rn(a.x * s, a.y * s);
    pk.h[1] = __floats2half2_rn(a.z * s, a.w * s);
    pk.h[2] = __floats2half2_rn(b.x * s, b.y * s);
    pk.h[3] = __floats2half2_rn(b.z * s, b.w * s);
    *(uint4*)(g_Wh + base) = pk.u;
}

__global__ void xconv_kernel(const float* __restrict__ x) {
    size_t base = ((size_t)blockIdx.x * 256 + threadIdx.x) * 8;
    float4 a = *(const float4*)(x + base);
    float4 b = *(const float4*)(x + base + 4);
    union { __half2 h[4]; uint4 u; } pk;
    pk.h[0] = __floats2half2_rn(a.x, a.y);
    pk.h[1] = __floats2half2_rn(a.z, a.w);
    pk.h[2] = __floats2half2_rn(b.x, b.y);
    pk.h[3] = __floats2half2_rn(b.z, b.w);
    *(uint4*)(g_Xh + base) = pk.u;
}

// ------------------------------ GEMM kernel --------------------------------
// smem per stage: A[128 rows][32 halves] then B[256 rows][32 halves], 64B rows
// XOR-swizzled in 16B chunks: c ^= (row>>1)&3. Conflict-free for cp.async
// writes and all ldmatrix phases.
__global__ void __launch_bounds__(256, 1) gemm_kernel(float* __restrict__ out) {
    extern __shared__ char smem_raw[];
    const uint32_t sbase = smem_u32(smem_raw);
    const int tid = threadIdx.x;
    const int wid = tid >> 5;
    const int lane = tid & 31;
    const int warp_m = wid & 1;    // 2 warps along M (64 rows each)
    const int warp_n = wid >> 1;   // 4 warps along N (64 cols each)

    // rasterize for L2 reuse
    const int num_n = DN / BN;     // 16
    const int GROUP_M = 8;
    int bid = blockIdx.x;
    int tpg = GROUP_M * num_n;     // 128
    int group = bid / tpg;
    int rem = bid - group * tpg;
    int mt_blk = group * GROUP_M + (rem % GROUP_M);
    int nt_blk = rem / GROUP_M;
    const size_t m0 = (size_t)mt_blk * BM;
    const size_t n0 = (size_t)nt_blk * BN;

    const __half* gA = g_Xh + m0 * DK;
    const __half* gB = g_Wh + n0 * DK;

    auto load_stage = [&](int s, int kc) {
        uint32_t base = sbase + s * STAGE_BYTES;
        int k0 = kc * BK;
#pragma unroll
        for (int j = 0; j < 2; j++) {          // A: 128 rows x 4 chunks
            int i = tid + j * 256;
            int row = i >> 2;
            int c = i & 3;
            uint32_t off = (uint32_t)(row * 64 + ((c ^ ((row >> 1) & 3)) * 16));
            cp_async16(base + off, gA + (size_t)row * DK + k0 + c * 8);
        }
#pragma unroll
        for (int j = 0; j < 4; j++) {          // B: 256 rows x 4 chunks
            int i = tid + j * 256;
            int row = i >> 2;
            int c = i & 3;
            uint32_t off = (uint32_t)(row * 64 + ((c ^ ((row >> 1) & 3)) * 16));
            cp_async16(base + TILE_A_BYTES + off, gB + (size_t)row * DK + k0 + c * 8);
        }
    };

    // per-thread ldmatrix address components (xor term constant across tiles:
    // tile strides are 16 rows, and (16>>1)&3 == 0)
    const int rowA = warp_m * 64 + (lane & 15);
    const int xa = (rowA >> 1) & 3;
    const uint32_t offA = (uint32_t)(rowA * 64);
    const int rowB = warp_n * 64 + ((lane >> 4) << 3) + (lane & 7);
    const int xb = (rowB >> 1) & 3;
    const uint32_t offB = (uint32_t)(rowB * 64);

    float acc[4][8][4];
#pragma unroll
    for (int mt = 0; mt < 4; mt++)
#pragma unroll
        for (int nt = 0; nt < 8; nt++)
#pragma unroll
            for (int r = 0; r < 4; r++) acc[mt][nt][r] = 0.f;

    // prologue: stages 0..2
#pragma unroll
    for (int s = 0; s < STAGES - 1; s++) { load_stage(s, s); cp_commit(); }

    for (int it = 0; it < NITER; it++) {
        cp_wait<STAGES - 2>();
        __syncthreads();

        int kc = it + STAGES - 1;
        if (kc < NITER) load_stage(kc & (STAGES - 1), kc);
        cp_commit();

        const uint32_t stA = sbase + (it & (STAGES - 1)) * STAGE_BYTES;
        const uint32_t stB = stA + TILE_A_BYTES;
#pragma unroll
        for (int s16 = 0; s16 < 2; s16++) {
            uint32_t a[4][4];
            uint32_t b[8][2];
            const int cA = (s16 * 2 + (lane >> 4)) ^ xa;
#pragma unroll
            for (int mt = 0; mt < 4; mt++)
                ldmx4(a[mt], stA + offA + mt * 1024 + cA * 16);
            const int cB = (s16 * 2 + ((lane >> 3) & 1)) ^ xb;
#pragma unroll
            for (int h = 0; h < 4; h++) {      // 4 x (16 rows of B) = 64 cols
                uint32_t r[4];
                ldmx4(r, stB + offB + h * 1024 + cB * 16);
                b[h * 2 + 0][0] = r[0]; b[h * 2 + 0][1] = r[1];
                b[h * 2 + 1][0] = r[2]; b[h * 2 + 1][1] = r[3];
            }
#pragma unroll
            for (int mt = 0; mt < 4; mt++)
#pragma unroll
                for (int nt = 0; nt < 8; nt++)
                    mma16816(acc[mt][nt], a[mt], b[nt]);
        }
    }

    // epilogue: direct global stores (float2 per fragment pair)
    float* op = out + m0 * DN + n0;
#pragma unroll
    for (int mt = 0; mt < 4; mt++) {
        int r0 = warp_m * 64 + mt * 16 + (lane >> 2);
#pragma unroll
        for (int nt = 0; nt < 8; nt++) {
            int col = warp_n * 64 + nt * 8 + (lane & 3) * 2;
            float2* p0 = (float2*)(op + (size_t)r0 * DN + col);
            float2* p1 = (float2*)(op + (size_t)(r0 + 8) * DN + col);
            *p0 = make_float2(acc[mt][nt][0], acc[mt][nt][1]);
            *p1 = make_float2(acc[mt][nt][2], acc[mt][nt][3]);
        }
    }
}

// ------------------------------ launch -------------------------------------
extern "C" void kernel_launch(void* const* d_in, const int* in_sizes, int n_in,
                              void* d_out, int out_size) {
    (void)in_sizes; (void)n_in; (void)out_size;
    const float* x       = (const float*)d_in[0];
    const float* signs   = (const float*)d_in[1];
    const float* ps      = (const float*)d_in[2];
    const float* routing = (const float*)d_in[3];
    float* out = (float*)d_out;

    cudaFuncSetAttribute(gemm_kernel, cudaFuncAttributeMaxDynamicSharedMemorySize,
                         SMEM_TOTAL);

    blend_kernel<<<NGROUPS / 256, 256>>>(ps, routing);
    weight_kernel<<<(int)(((size_t)DN * DK / 8) / 256), 256>>>(signs);
    xconv_kernel<<<(int)(((size_t)DM * DK / 8) / 256), 256>>>(x);
    gemm_kernel<<<(DM / BM) * (DN / BN), 256, SMEM_TOTAL>>>(out);
}

// round 5
// speedup vs baseline: 2.0100x; 2.0100x over previous
#include <cuda_runtime.h>
#include <cuda_fp16.h>
#include <cstdint>

// ---------------------------------------------------------------------------
// RoutedBitLinear: out[M,N] = x[M,K] @ (signs * blended_scales)[N,K]^T
// M=8192, N=4096, K=4096, group_size=128, P=8.
// mma.sync.m16n8k16 f16 path (tcgen05 unavailable: harness PTX target sm_103).
// R5: CTA 128x128 with 4 warps (128 thr), warp tile 64x64, 2 CTAs/SM.
// Rationale: R3 was smem-crossbar co-bound (96KB reads/SM-iter ~= tensor time);
// 64x64 warp tile cuts smem bytes/FLOP 1.5x. R4 showed one 8-warp CTA
// phase-locks its ld/MMA phases -> tensor bubbles; two independent 4-warp
// CTAs de-phase and overlap (the structure that made R3 work).
// ---------------------------------------------------------------------------

#define DM 8192
#define DN 4096
#define DK 4096
#define NGROUPS (DN * DK / 128)   // 131072

#define BM 128
#define BN 128
#define BK 32                      // halves per k-chunk
#define STAGES 4
#define NITER (DK / BK)            // 128
#define TILE_A_BYTES (BM * BK * 2) // 8192
#define STAGE_BYTES (2 * TILE_A_BYTES)      // 16384 (A + B)
#define SMEM_TOTAL (STAGES * STAGE_BYTES)   // 65536 -> 2 CTAs/SM

// Scratch (static device globals: allocation-free per harness rules)
__device__ __align__(256) __half g_Wh[(size_t)DN * DK];   // 32 MB
__device__ __align__(256) __half g_Xh[(size_t)DM * DK];   // 64 MB
__device__ float g_blend[NGROUPS];

// ------------------------------ helpers ------------------------------------
__device__ __forceinline__ uint32_t smem_u32(const void* p) {
    return (uint32_t)__cvta_generic_to_shared(p);
}
__device__ __forceinline__ void cp_async16(uint32_t dst, const void* src) {
    asm volatile("cp.async.cg.shared.global [%0], [%1], 16;" :: "r"(dst), "l"(src));
}
__device__ __forceinline__ void cp_commit() {
    asm volatile("cp.async.commit_group;");
}
template <int Npend>
__device__ __forceinline__ void cp_wait() {
    asm volatile("cp.async.wait_group %0;" :: "n"(Npend));
}
__device__ __forceinline__ void ldmx4(uint32_t* d, uint32_t addr) {
    asm volatile("ldmatrix.sync.aligned.m8n8.x4.shared.b16 {%0,%1,%2,%3}, [%4];"
                 : "=r"(d[0]), "=r"(d[1]), "=r"(d[2]), "=r"(d[3]) : "r"(addr));
}
__device__ __forceinline__ void mma16816(float* c, const uint32_t* a, const uint32_t* b) {
    asm volatile(
        "mma.sync.aligned.m16n8k16.row.col.f32.f16.f16.f32 "
        "{%0,%1,%2,%3}, {%4,%5,%6,%7}, {%8,%9}, {%0,%1,%2,%3};"
        : "+f"(c[0]), "+f"(c[1]), "+f"(c[2]), "+f"(c[3])
        : "r"(a[0]), "r"(a[1]), "r"(a[2]), "r"(a[3]), "r"(b[0]), "r"(b[1]));
}

// ------------------------------ prep kernels -------------------------------
__global__ void blend_kernel(const float* __restrict__ ps, const float* __restrict__ rt) {
    int g = blockIdx.x * 256 + threadIdx.x;
    float acc = 0.f;
#pragma unroll
    for (int p = 0; p < 8; p++)
        acc = fmaf(rt[p], ps[(size_t)p * NGROUPS + g], acc);
    g_blend[g] = acc;
}

__global__ void weight_kernel(const float* __restrict__ signs) {
    size_t base = ((size_t)blockIdx.x * 256 + threadIdx.x) * 8;
    float s = g_blend[base >> 7];  // flat index >> 7 == o*32 + i/128
    float4 a = *(const float4*)(signs + base);
    float4 b = *(const float4*)(signs + base + 4);
    union { __half2 h[4]; uint4 u; } pk;
    pk.h[0] = __floats2half2_rn(a.x * s, a.y * s);
    pk.h[1] = __floats2half2_rn(a.z * s, a.w * s);
    pk.h[2] = __floats2half2_rn(b.x * s, b.y * s);
    pk.h[3] = __floats2half2_rn(b.z * s, b.w * s);
    *(uint4*)(g_Wh + base) = pk.u;
}

__global__ void xconv_kernel(const float* __restrict__ x) {
    size_t base = ((size_t)blockIdx.x * 256 + threadIdx.x) * 8;
    float4 a = *(const float4*)(x + base);
    float4 b = *(const float4*)(x + base + 4);
    union { __half2 h[4]; uint4 u; } pk;
    pk.h[0] = __floats2half2_rn(a.x, a.y);
    pk.h[1] = __floats2half2_rn(a.z, a.w);
    pk.h[2] = __floats2half2_rn(b.x, b.y);
    pk.h[3] = __floats2half2_rn(b.z, b.w);
    *(uint4*)(g_Xh + base) = pk.u;
}

// ------------------------------ GEMM kernel --------------------------------
// smem per stage: A[128 rows][32 halves] then B[128 rows][32 halves], 64B rows
// XOR-swizzled in 16B chunks: c ^= (row>>1)&3. Conflict-free for cp.async
// writes and all ldmatrix phases.
__global__ void __launch_bounds__(128, 2) gemm_kernel(float* __restrict__ out) {
    extern __shared__ char smem_raw[];
    const uint32_t sbase = smem_u32(smem_raw);
    const int tid = threadIdx.x;
    const int wid = tid >> 5;
    const int lane = tid & 31;
    const int warp_m = wid & 1;    // 2 warps along M (64 rows each)
    const int warp_n = wid >> 1;   // 2 warps along N (64 cols each)

    // rasterize for L2 reuse
    const int num_n = DN / BN;     // 32
    const int GROUP_M = 16;
    int bid = blockIdx.x;
    int tpg = GROUP_M * num_n;     // 512
    int group = bid / tpg;
    int rem = bid - group * tpg;
    int mt_blk = group * GROUP_M + (rem % GROUP_M);
    int nt_blk = rem / GROUP_M;
    const size_t m0 = (size_t)mt_blk * BM;
    const size_t n0 = (size_t)nt_blk * BN;

    const __half* gA = g_Xh + m0 * DK;
    const __half* gB = g_Wh + n0 * DK;

    auto load_stage = [&](int s, int kc) {
        uint32_t base = sbase + s * STAGE_BYTES;
        int k0 = kc * BK;
#pragma unroll
        for (int j = 0; j < 4; j++) {          // A then B: 128 rows x 4 chunks each
            int i = tid + j * 128;             // 0..511
            int row = i >> 2;
            int c = i & 3;
            uint32_t off = (uint32_t)(row * 64 + ((c ^ ((row >> 1) & 3)) * 16));
            cp_async16(base + off, gA + (size_t)row * DK + k0 + c * 8);
            cp_async16(base + TILE_A_BYTES + off, gB + (size_t)row * DK + k0 + c * 8);
        }
    };

    // per-thread ldmatrix address components (xor term constant across mt/h
    // tiles: tile strides are 16 rows, and (16>>1)&3 == 0)
    const int rowA = warp_m * 64 + (lane & 15);
    const int xa = (rowA >> 1) & 3;
    const uint32_t offA = (uint32_t)(rowA * 64);
    const int rowB = warp_n * 64 + ((lane >> 4) << 3) + (lane & 7);
    const int xb = (rowB >> 1) & 3;
    const uint32_t offB = (uint32_t)(rowB * 64);

    float acc[4][8][4];
#pragma unroll
    for (int mt = 0; mt < 4; mt++)
#pragma unroll
        for (int nt = 0; nt < 8; nt++)
#pragma unroll
            for (int r = 0; r < 4; r++) acc[mt][nt][r] = 0.f;

    // prologue: stages 0..2
#pragma unroll
    for (int s = 0; s < STAGES - 1; s++) { load_stage(s, s); cp_commit(); }

    for (int it = 0; it < NITER; it++) {
        cp_wait<STAGES - 2>();
        __syncthreads();

        int kc = it + STAGES - 1;
        if (kc < NITER) load_stage(kc & (STAGES - 1), kc);
        cp_commit();

        const uint32_t stA = sbase + (it & (STAGES - 1)) * STAGE_BYTES;
        const uint32_t stB = stA + TILE_A_BYTES;
#pragma unroll
        for (int s16 = 0; s16 < 2; s16++) {
            uint32_t a[4][4];
            uint32_t b[8][2];
            const int cA = (s16 * 2 + (lane >> 4)) ^ xa;
#pragma unroll
            for (int mt = 0; mt < 4; mt++)
                ldmx4(a[mt], stA + offA + mt * 1024 + cA * 16);
            const int cB = (s16 * 2 + ((lane >> 3) & 1)) ^ xb;
#pragma unroll
            for (int h = 0; h < 4; h++) {      // 4 x (16 rows of B) = 64 cols
                uint32_t r[4];
                ldmx4(r, stB + offB + h * 1024 + cB * 16);
                b[h * 2 + 0][0] = r[0]; b[h * 2 + 0][1] = r[1];
                b[h * 2 + 1][0] = r[2]; b[h * 2 + 1][1] = r[3];
            }
#pragma unroll
            for (int mt = 0; mt < 4; mt++)
#pragma unroll
                for (int nt = 0; nt < 8; nt++)
                    mma16816(acc[mt][nt], a[mt], b[nt]);
        }
    }

    // epilogue: direct global stores (float2 per fragment pair)
    float* op = out + m0 * DN + n0;
#pragma unroll
    for (int mt = 0; mt < 4; mt++) {
        int r0 = warp_m * 64 + mt * 16 + (lane >> 2);
#pragma unroll
        for (int nt = 0; nt < 8; nt++) {
            int col = warp_n * 64 + nt * 8 + (lane & 3) * 2;
            float2* p0 = (float2*)(op + (size_t)r0 * DN + col);
            float2* p1 = (float2*)(op + (size_t)(r0 + 8) * DN + col);
            *p0 = make_float2(acc[mt][nt][0], acc[mt][nt][1]);
            *p1 = make_float2(acc[mt][nt][2], acc[mt][nt][3]);
        }
    }
}

// ------------------------------ launch -------------------------------------
extern "C" void kernel_launch(void* const* d_in, const int* in_sizes, int n_in,
                              void* d_out, int out_size) {
    (void)in_sizes; (void)n_in; (void)out_size;
    const float* x       = (const float*)d_in[0];
    const float* signs   = (const float*)d_in[1];
    const float* ps      = (const float*)d_in[2];
    const float* routing = (const float*)d_in[3];
    float* out = (float*)d_out;

    cudaFuncSetAttribute(gemm_kernel, cudaFuncAttributeMaxDynamicSharedMemorySize,
                         SMEM_TOTAL);

    blend_kernel<<<NGROUPS / 256, 256>>>(ps, routing);
    weight_kernel<<<(int)(((size_t)DN * DK / 8) / 256), 256>>>(signs);
    xconv_kernel<<<(int)(((size_t)DM * DK / 8) / 256), 256>>>(x);
    gemm_kernel<<<(DM / BM) * (DN / BN), 128, SMEM_TOTAL>>>(out);
}